// round 5
// baseline (speedup 1.0000x reference)
#include <cuda_runtime.h>

// CapsuleLayer: x[B,I,D] fp32, W[I,O,D,K] fp32 -> v[B,O,K] fp32
// B=64, I=2048, D=8, O=32, K=16, 3 routing rounds.
// Routing logits are linear in v:  b_r[b,o,i] = u_hat[b,o,i,:] . Vsum_r[b,o,:]
// => each round = ONE fused sweep over i recomputing u_hat in registers.
// Round 5: 256-thread blocks x 2 blocks/SM so softmax barriers in one block
// overlap FMAs in the other; 1-2 barriers per i; no-max softmax.

#define BB 64
#define II 2048
#define DD 8
#define OO 32
#define KK 16
#define BG 16            // b's per block (2 per thread)
#define IC 32            // i's per block
#define NBUF 3
#define NP (II/IC)       // 64 partial slabs
#define SVOL (BB*OO*KK)  // 32768

#define WROWF 132                 // padded floats per o-row
#define WSLABF (OO*WROWF)         // 4224 floats (one i)
#define XROWF 12
#define XSLABF (BG*XROWF)         // 192 floats
#define SLABF  (WSLABF + XSLABF)  // 4416 floats
#define AG_OFF (NBUF*SLABF)       // 13248 floats
#define AGROW  33
#define SMEM_BYTES ((AG_OFF + BG*AGROW) * 4)   // 55104 B

__device__ float g_part[NP * SVOL];  // per-i-block partial s (8.4 MB)
__device__ float g_vsum[SVOL];       // running sum of squashed v's

// ---------- packed f32x2 helpers ----------
__device__ __forceinline__ unsigned long long pk2(float lo, float hi) {
    unsigned long long r;
    asm("mov.b64 %0, {%1, %2};" : "=l"(r) : "f"(lo), "f"(hi));
    return r;
}
__device__ __forceinline__ void upk2(unsigned long long v, float& lo, float& hi) {
    asm("mov.b64 {%0, %1}, %2;" : "=f"(lo), "=f"(hi) : "l"(v));
}
__device__ __forceinline__ unsigned long long fma2(unsigned long long a,
                                                   unsigned long long b,
                                                   unsigned long long c) {
    unsigned long long d;
    asm("fma.rn.f32x2 %0, %1, %2, %3;" : "=l"(d) : "l"(a), "l"(b), "l"(c));
    return d;
}

// ---------- cp.async helpers ----------
__device__ __forceinline__ void cp16(unsigned dst_smem, const void* src) {
    asm volatile("cp.async.cg.shared.global [%0], [%1], 16;"
                 :: "r"(dst_smem), "l"(src));
}
__device__ __forceinline__ void cp_commit() {
    asm volatile("cp.async.commit_group;");
}
template<int N>
__device__ __forceinline__ void cp_wait() {
    asm volatile("cp.async.wait_group %0;" :: "n"(N) : "memory");
}

// Stage one i (W row-tile + x column) into buffer `buf`. One commit group.
__device__ __forceinline__ void fill_slab(unsigned sm_addr,
                                          const float* __restrict__ W,
                                          const float* __restrict__ x,
                                          int i, int buf, int t, int bg) {
    // W: 1024 float4 chunks, 4 per thread (256 threads)
#pragma unroll
    for (int r = 0; r < 4; r++) {
        int c = t + r * 256;
        int o = c >> 5, w16 = c & 31;
        const float* src = W + ((size_t)i * OO + o) * (DD * KK) + w16 * 4;
        unsigned dst = sm_addr + (unsigned)((buf * SLABF + o * WROWF + w16 * 4) * 4);
        cp16(dst, src);
    }
    // x: BG*2 = 32 float4 chunks (threads 0..31)
    if (t < BG * 2) {
        int b = t >> 1, half = t & 1;
        const float* src = x + ((size_t)(bg * BG + b) * II + i) * DD + half * 4;
        unsigned dst = sm_addr +
            (unsigned)((buf * SLABF + WSLABF + b * XROWF + half * 4) * 4);
        cp16(dst, src);
    }
    cp_commit();
}

// Fused routing pass. 256 threads: t = o*8 + tb; thread handles b = tb, tb+8.
template<bool FIRST>
__global__ __launch_bounds__(256, 2)
void pass_kernel(const float* __restrict__ x, const float* __restrict__ W) {
    extern __shared__ float sm[];
    const unsigned sm_addr = (unsigned)__cvta_generic_to_shared(sm);
    float* ag = sm + AG_OFF;

    const int t  = threadIdx.x;
    const int o  = t >> 3;
    const int tb = t & 7;
    const int bg = blockIdx.y;
    const int b0 = bg * BG + tb;
    const int b1 = b0 + 8;
    const int i0 = blockIdx.x * IC;

    // prologue: slabs 0,1
    fill_slab(sm_addr, W, x, i0,     0, t, bg);
    fill_slab(sm_addr, W, x, i0 + 1, 1, t, bg);

    // Vsum for (b0,o),(b1,o), packed
    unsigned long long Va[8], Vb[8];
    if (!FIRST) {
        const ulonglong2* vp0 =
            reinterpret_cast<const ulonglong2*>(g_vsum + ((size_t)b0 * OO + o) * KK);
        const ulonglong2* vp1 =
            reinterpret_cast<const ulonglong2*>(g_vsum + ((size_t)b1 * OO + o) * KK);
#pragma unroll
        for (int j = 0; j < 4; j++) {
            ulonglong2 q0 = vp0[j]; Va[2*j] = q0.x; Va[2*j+1] = q0.y;
            ulonglong2 q1 = vp1[j]; Vb[2*j] = q1.x; Vb[2*j+1] = q1.y;
        }
    }

    unsigned long long sa[8], sb[8];
#pragma unroll
    for (int j = 0; j < 8; j++) { sa[j] = 0ull; sb[j] = 0ull; }

    cp_wait<1>();        // slab 0 resident
    __syncthreads();     // visible block-wide

    for (int s = 0; s < IC; s++) {
        // refill: overwrites slab s-1's buffer; safe — all slab s-1 reads
        // completed before the end-of-iteration barrier we just passed.
        if (s + 2 < IC)
            fill_slab(sm_addr, W, x, i0 + s + 2, (s + 2) % NBUF, t, bg);

        const float* slab = sm + (s % NBUF) * SLABF;

        // x rows for b0, b1
        float xf0[8], xf1[8];
        {
            const float4* xr0 = reinterpret_cast<const float4*>(
                slab + WSLABF + tb * XROWF);
            const float4* xr1 = reinterpret_cast<const float4*>(
                slab + WSLABF + (tb + 8) * XROWF);
            float4 a0 = xr0[0], a1 = xr0[1];
            float4 c0 = xr1[0], c1 = xr1[1];
            xf0[0]=a0.x; xf0[1]=a0.y; xf0[2]=a0.z; xf0[3]=a0.w;
            xf0[4]=a1.x; xf0[5]=a1.y; xf0[6]=a1.z; xf0[7]=a1.w;
            xf1[0]=c0.x; xf1[1]=c0.y; xf1[2]=c0.z; xf1[3]=c0.w;
            xf1[4]=c1.x; xf1[5]=c1.y; xf1[6]=c1.z; xf1[7]=c1.w;
        }

        unsigned long long ua[8], ub[8];
#pragma unroll
        for (int j = 0; j < 8; j++) { ua[j] = 0ull; ub[j] = 0ull; }

        const float* wrow = slab + o * WROWF;
#pragma unroll
        for (int d = 0; d < DD; d++) {
            const ulonglong2* wp = reinterpret_cast<const ulonglong2*>(wrow + d * 16);
            unsigned long long xa2 = pk2(xf0[d], xf0[d]);
            unsigned long long xb2 = pk2(xf1[d], xf1[d]);
            ulonglong2 q0 = wp[0], q1 = wp[1];
            ua[0] = fma2(xa2, q0.x, ua[0]);  ub[0] = fma2(xb2, q0.x, ub[0]);
            ua[1] = fma2(xa2, q0.y, ua[1]);  ub[1] = fma2(xb2, q0.y, ub[1]);
            ua[2] = fma2(xa2, q1.x, ua[2]);  ub[2] = fma2(xb2, q1.x, ub[2]);
            ua[3] = fma2(xa2, q1.y, ua[3]);  ub[3] = fma2(xb2, q1.y, ub[3]);
            ulonglong2 q2 = wp[2], q3 = wp[3];
            ua[4] = fma2(xa2, q2.x, ua[4]);  ub[4] = fma2(xb2, q2.x, ub[4]);
            ua[5] = fma2(xa2, q2.y, ua[5]);  ub[5] = fma2(xb2, q2.y, ub[5]);
            ua[6] = fma2(xa2, q3.x, ua[6]);  ub[6] = fma2(xb2, q3.x, ub[6]);
            ua[7] = fma2(xa2, q3.y, ua[7]);  ub[7] = fma2(xb2, q3.y, ub[7]);
        }

        if (FIRST) {
            const unsigned long long c2 = pk2(1.0f / OO, 1.0f / OO);
#pragma unroll
            for (int j = 0; j < 8; j++) {
                sa[j] = fma2(c2, ua[j], sa[j]);
                sb[j] = fma2(c2, ub[j], sb[j]);
            }
            // ensure slab s+1 resident, then one barrier ends the iteration
            if (s + 1 < IC) cp_wait<1>(); else cp_wait<0>();
            __syncthreads();
        } else {
            // agreement = u . Vsum
            unsigned long long acca = 0ull, accb = 0ull;
#pragma unroll
            for (int j = 0; j < 8; j++) {
                acca = fma2(ua[j], Va[j], acca);
                accb = fma2(ub[j], Vb[j], accb);
            }
            float al, ah, bl2, bh;
            upk2(acca, al, ah);
            upk2(accb, bl2, bh);
            ag[tb * AGROW + o]       = al + ah;
            ag[(tb + 8) * AGROW + o] = bl2 + bh;
            __syncthreads();                 // barrier 1: agr visible

            // warp w: softmax rows w and w+8 (lane = o). No max-subtract:
            // |agr| <= |u||Vsum| is O(1), exp is safe in fp32.
            {
                int w = t >> 5, lane = t & 31;
                float e0 = __expf(ag[w * AGROW + lane]);
                float e1 = __expf(ag[(w + 8) * AGROW + lane]);
                float s0 = e0, s1 = e1;
#pragma unroll
                for (int st = 16; st > 0; st >>= 1) {
                    s0 += __shfl_xor_sync(0xffffffffu, s0, st);
                    s1 += __shfl_xor_sync(0xffffffffu, s1, st);
                }
                ag[w * AGROW + lane]       = __fdividef(e0, s0);
                ag[(w + 8) * AGROW + lane] = __fdividef(e1, s1);
            }
            // overlap the next-slab wait with softmax, then barrier 2
            if (s + 1 < IC) cp_wait<1>(); else cp_wait<0>();
            __syncthreads();                 // barrier 2: c visible + slab s+1 visible

            float ca = ag[tb * AGROW + o];
            float cb = ag[(tb + 8) * AGROW + o];
            unsigned long long c2a = pk2(ca, ca);
            unsigned long long c2b = pk2(cb, cb);
#pragma unroll
            for (int j = 0; j < 8; j++) {
                sa[j] = fma2(c2a, ua[j], sa[j]);
                sb[j] = fma2(c2b, ub[j], sb[j]);
            }
        }
    }

    // flush partials
    ulonglong2* p0 = reinterpret_cast<ulonglong2*>(
        g_part + ((size_t)blockIdx.x * SVOL + ((size_t)b0 * OO + o) * KK));
    ulonglong2* p1 = reinterpret_cast<ulonglong2*>(
        g_part + ((size_t)blockIdx.x * SVOL + ((size_t)b1 * OO + o) * KK));
    p0[0] = make_ulonglong2(sa[0], sa[1]);
    p0[1] = make_ulonglong2(sa[2], sa[3]);
    p0[2] = make_ulonglong2(sa[4], sa[5]);
    p0[3] = make_ulonglong2(sa[6], sa[7]);
    p1[0] = make_ulonglong2(sb[0], sb[1]);
    p1[1] = make_ulonglong2(sb[2], sb[3]);
    p1[2] = make_ulonglong2(sb[4], sb[5]);
    p1[3] = make_ulonglong2(sb[6], sb[7]);
}

// Reduce partials over NP slabs (float4 per thread), squash over K=16.
// Capsule = 4 consecutive float4-threads; reduce s2 over lanes xor 1,2.
// phase 0: vsum = v ; phase 1: vsum += v ; phase 2: out = v
__global__ void squash_kernel(float* __restrict__ out, int phase) {
    int tid = blockIdx.x * 256 + threadIdx.x;     // 0..8191 (SVOL/4)
    const float4* gp = reinterpret_cast<const float4*>(g_part);
    float4 s = make_float4(0.f, 0.f, 0.f, 0.f);
#pragma unroll 8
    for (int p = 0; p < NP; p++) {
        float4 q = gp[(size_t)p * (SVOL / 4) + tid];
        s.x += q.x; s.y += q.y; s.z += q.z; s.w += q.w;
    }

    float s2 = s.x * s.x + s.y * s.y + s.z * s.z + s.w * s.w;
    s2 += __shfl_xor_sync(0xffffffffu, s2, 1);
    s2 += __shfl_xor_sync(0xffffffffu, s2, 2);

    float scale = s2 / ((1.0f + s2) * sqrtf(s2 + 1e-7f));
    float4 v = make_float4(scale * s.x, scale * s.y, scale * s.z, scale * s.w);

    if (phase == 0) {
        reinterpret_cast<float4*>(g_vsum)[tid] = v;
    } else if (phase == 1) {
        float4* vp = reinterpret_cast<float4*>(g_vsum);
        float4 old = vp[tid];
        vp[tid] = make_float4(old.x + v.x, old.y + v.y, old.z + v.z, old.w + v.w);
    } else {
        reinterpret_cast<float4*>(out)[tid] = v;
    }
}

extern "C" void kernel_launch(void* const* d_in, const int* in_sizes, int n_in,
                              void* d_out, int out_size) {
    const float* a0 = (const float*)d_in[0];
    const float* a1 = (const float*)d_in[1];
    const float* x;
    const float* W;
    if (in_sizes[0] == BB * II * DD) { x = a0; W = a1; }
    else                             { x = a1; W = a0; }
    float* out = (float*)d_out;

    cudaFuncSetAttribute(pass_kernel<true>,
                         cudaFuncAttributeMaxDynamicSharedMemorySize, SMEM_BYTES);
    cudaFuncSetAttribute(pass_kernel<false>,
                         cudaFuncAttributeMaxDynamicSharedMemorySize, SMEM_BYTES);

    dim3 pg(II / IC, BB / BG);     // (64, 4) = 256 blocks, 256 threads
    const int rb = (SVOL / 4) / 256;  // 32 blocks for squash

    pass_kernel<true><<<pg, 256, SMEM_BYTES>>>(x, W);    // s0 (uniform c)
    squash_kernel<<<rb, 256>>>(out, 0);                  // v0 -> Vsum

    pass_kernel<false><<<pg, 256, SMEM_BYTES>>>(x, W);   // s1 (vs v0)
    squash_kernel<<<rb, 256>>>(out, 1);                  // Vsum += v1

    pass_kernel<false><<<pg, 256, SMEM_BYTES>>>(x, W);   // s2 (vs v0+v1)
    squash_kernel<<<rb, 256>>>(out, 2);                  // v2 = output
}

// round 6
// speedup vs baseline: 1.0122x; 1.0122x over previous
#include <cuda_runtime.h>

// CapsuleLayer: x[B,I,D] fp32, W[I,O,D,K] fp32 -> v[B,O,K] fp32
// B=64, I=2048, D=8, O=32, K=16, 3 routing rounds.
// Routing logits are linear in v:  b_r[b,o,i] = u_hat[b,o,i,:] . Vsum_r[b,o,:]
// => each round = ONE fused sweep over i recomputing u_hat in registers.
// Round 6: warp = all 32 o's of one b (t = tb*32 + o) -> softmax is
// warp-local (shuffles only, ZERO block barriers per i). Slab barriers
// only: 1 per 2 i. W LDS rows are conflict-free via 132-float stride.

#define BB 64
#define II 2048
#define DD 8
#define OO 32
#define KK 16
#define BG 32            // b's per block (2 per thread)
#define IC 32            // i's per block
#define SUB 2            // i's per slab
#define NSLAB (IC/SUB)   // 16
#define NBUF 3
#define NP (II/IC)       // 64 partial slabs
#define SVOL (BB*OO*KK)  // 32768

#define WROWF 132                  // padded floats per o-row (stride 4 banks)
#define WSLABF (SUB*OO*WROWF)      // 8448 floats
#define XROWF 12
#define XSLABF (SUB*BG*XROWF)      // 768 floats
#define SLABF  (WSLABF + XSLABF)   // 9216 floats
#define SMEM_BYTES (NBUF * SLABF * 4)   // 110592 B

__device__ float g_part[NP * SVOL];  // per-i-block partial s (8.4 MB)
__device__ float g_vsum[SVOL];       // running sum of squashed v's

// ---------- packed f32x2 helpers ----------
__device__ __forceinline__ unsigned long long pk2(float lo, float hi) {
    unsigned long long r;
    asm("mov.b64 %0, {%1, %2};" : "=l"(r) : "f"(lo), "f"(hi));
    return r;
}
__device__ __forceinline__ void upk2(unsigned long long v, float& lo, float& hi) {
    asm("mov.b64 {%0, %1}, %2;" : "=f"(lo), "=f"(hi) : "l"(v));
}
__device__ __forceinline__ unsigned long long fma2(unsigned long long a,
                                                   unsigned long long b,
                                                   unsigned long long c) {
    unsigned long long d;
    asm("fma.rn.f32x2 %0, %1, %2, %3;" : "=l"(d) : "l"(a), "l"(b), "l"(c));
    return d;
}

// ---------- cp.async helpers ----------
__device__ __forceinline__ void cp16(unsigned dst_smem, const void* src) {
    asm volatile("cp.async.cg.shared.global [%0], [%1], 16;"
                 :: "r"(dst_smem), "l"(src));
}
__device__ __forceinline__ void cp_commit() {
    asm volatile("cp.async.commit_group;");
}
template<int N>
__device__ __forceinline__ void cp_wait() {
    asm volatile("cp.async.wait_group %0;" :: "n"(N) : "memory");
}

// Stage one slab (SUB i's of W + x) into buffer `buf`. One commit group.
__device__ __forceinline__ void fill_slab(unsigned sm_addr,
                                          const float* __restrict__ W,
                                          const float* __restrict__ x,
                                          int i_base, int buf, int t, int bg) {
    // W: SUB*1024 = 2048 float4 chunks, 4 per thread (512 threads)
#pragma unroll
    for (int r = 0; r < 4; r++) {
        int c = t + r * 512;
        int isub = c >> 10, rem = c & 1023;
        int o = rem >> 5, w16 = rem & 31;
        const float* src = W + ((size_t)(i_base + isub) * OO + o) * (DD * KK) + w16 * 4;
        unsigned dst = sm_addr +
            (unsigned)((buf * SLABF + isub * (OO * WROWF) + o * WROWF + w16 * 4) * 4);
        cp16(dst, src);
    }
    // x: SUB*BG*2 = 128 float4 chunks (threads 0..127)
    if (t < SUB * BG * 2) {
        int isub = t >> 6, b = (t >> 1) & 31, half = t & 1;
        const float* src = x + ((size_t)(bg * BG + b) * II + (i_base + isub)) * DD + half * 4;
        unsigned dst = sm_addr +
            (unsigned)((buf * SLABF + WSLABF + isub * (BG * XROWF) + b * XROWF + half * 4) * 4);
        cp16(dst, src);
    }
    cp_commit();
}

// Fused routing pass. 512 threads: warp w owns b = {bg*32+w, bg*32+w+16},
// lane = o. Softmax over o is warp-local.
template<bool FIRST>
__global__ __launch_bounds__(512, 1)
void pass_kernel(const float* __restrict__ x, const float* __restrict__ W) {
    extern __shared__ float sm[];
    const unsigned sm_addr = (unsigned)__cvta_generic_to_shared(sm);

    const int t    = threadIdx.x;
    const int w    = t >> 5;      // 0..15  (= tb)
    const int o    = t & 31;      // lane = o
    const int bg   = blockIdx.y;
    const int b0   = bg * BG + w;
    const int b1   = b0 + 16;
    const int i0   = blockIdx.x * IC;

    // prologue: slabs 0,1
    fill_slab(sm_addr, W, x, i0,        0, t, bg);
    fill_slab(sm_addr, W, x, i0 + SUB,  1, t, bg);

    // Vsum for (b0,o),(b1,o), packed
    unsigned long long Va[8], Vb[8];
    if (!FIRST) {
        const ulonglong2* vp0 =
            reinterpret_cast<const ulonglong2*>(g_vsum + ((size_t)b0 * OO + o) * KK);
        const ulonglong2* vp1 =
            reinterpret_cast<const ulonglong2*>(g_vsum + ((size_t)b1 * OO + o) * KK);
#pragma unroll
        for (int j = 0; j < 4; j++) {
            ulonglong2 q0 = vp0[j]; Va[2*j] = q0.x; Va[2*j+1] = q0.y;
            ulonglong2 q1 = vp1[j]; Vb[2*j] = q1.x; Vb[2*j+1] = q1.y;
        }
    }

    unsigned long long sa[8], sb[8];
#pragma unroll
    for (int j = 0; j < 8; j++) { sa[j] = 0ull; sb[j] = 0ull; }

    for (int s = 0; s < NSLAB; s++) {
        if (s + 1 < NSLAB) cp_wait<1>(); else cp_wait<0>();
        __syncthreads();   // slab s resident; all warps done with slab s-1
        if (s + 2 < NSLAB)
            fill_slab(sm_addr, W, x, i0 + (s + 2) * SUB, (s + 2) % NBUF, t, bg);

        const float* slab = sm + (s % NBUF) * SLABF;

#pragma unroll
        for (int isub = 0; isub < SUB; isub++) {
            // x rows for b0, b1 (broadcast within warp)
            float xf0[8], xf1[8];
            {
                const float4* xr0 = reinterpret_cast<const float4*>(
                    slab + WSLABF + isub * (BG * XROWF) + w * XROWF);
                const float4* xr1 = reinterpret_cast<const float4*>(
                    slab + WSLABF + isub * (BG * XROWF) + (w + 16) * XROWF);
                float4 a0 = xr0[0], a1 = xr0[1];
                float4 c0 = xr1[0], c1 = xr1[1];
                xf0[0]=a0.x; xf0[1]=a0.y; xf0[2]=a0.z; xf0[3]=a0.w;
                xf0[4]=a1.x; xf0[5]=a1.y; xf0[6]=a1.z; xf0[7]=a1.w;
                xf1[0]=c0.x; xf1[1]=c0.y; xf1[2]=c0.z; xf1[3]=c0.w;
                xf1[4]=c1.x; xf1[5]=c1.y; xf1[6]=c1.z; xf1[7]=c1.w;
            }

            unsigned long long ua[8], ub[8];
#pragma unroll
            for (int j = 0; j < 8; j++) { ua[j] = 0ull; ub[j] = 0ull; }

            // lane o reads its own W row (conflict-free: 132-float stride)
            const float* wrow = slab + isub * (OO * WROWF) + o * WROWF;
#pragma unroll
            for (int d = 0; d < DD; d++) {
                const ulonglong2* wp = reinterpret_cast<const ulonglong2*>(wrow + d * 16);
                unsigned long long xa2 = pk2(xf0[d], xf0[d]);
                unsigned long long xb2 = pk2(xf1[d], xf1[d]);
                ulonglong2 q0 = wp[0], q1 = wp[1];
                ua[0] = fma2(xa2, q0.x, ua[0]);  ub[0] = fma2(xb2, q0.x, ub[0]);
                ua[1] = fma2(xa2, q0.y, ua[1]);  ub[1] = fma2(xb2, q0.y, ub[1]);
                ua[2] = fma2(xa2, q1.x, ua[2]);  ub[2] = fma2(xb2, q1.x, ub[2]);
                ua[3] = fma2(xa2, q1.y, ua[3]);  ub[3] = fma2(xb2, q1.y, ub[3]);
                ulonglong2 q2 = wp[2], q3 = wp[3];
                ua[4] = fma2(xa2, q2.x, ua[4]);  ub[4] = fma2(xb2, q2.x, ub[4]);
                ua[5] = fma2(xa2, q2.y, ua[5]);  ub[5] = fma2(xb2, q2.y, ub[5]);
                ua[6] = fma2(xa2, q3.x, ua[6]);  ub[6] = fma2(xb2, q3.x, ub[6]);
                ua[7] = fma2(xa2, q3.y, ua[7]);  ub[7] = fma2(xb2, q3.y, ub[7]);
            }

            unsigned long long c2a, c2b;
            if (FIRST) {
                c2a = pk2(1.0f / OO, 1.0f / OO);
                c2b = c2a;
            } else {
                // agreement = u . Vsum  (per-thread over k)
                unsigned long long acca = 0ull, accb = 0ull;
#pragma unroll
                for (int j = 0; j < 8; j++) {
                    acca = fma2(ua[j], Va[j], acca);
                    accb = fma2(ub[j], Vb[j], accb);
                }
                float al, ah, bl2, bh;
                upk2(acca, al, ah);
                upk2(accb, bl2, bh);
                // softmax over o = over lanes, entirely in-warp.
                // No max-subtract: |agr| <= |u||Vsum| = O(1), exp safe in fp32.
                float e0 = __expf(al + ah);
                float e1 = __expf(bl2 + bh);
                float s0 = e0, s1 = e1;
#pragma unroll
                for (int st = 16; st > 0; st >>= 1) {
                    s0 += __shfl_xor_sync(0xffffffffu, s0, st);
                    s1 += __shfl_xor_sync(0xffffffffu, s1, st);
                }
                float ca = __fdividef(e0, s0);
                float cb = __fdividef(e1, s1);
                c2a = pk2(ca, ca);
                c2b = pk2(cb, cb);
            }

#pragma unroll
            for (int j = 0; j < 8; j++) {
                sa[j] = fma2(c2a, ua[j], sa[j]);
                sb[j] = fma2(c2b, ub[j], sb[j]);
            }
        }
    }

    // flush partials
    ulonglong2* p0 = reinterpret_cast<ulonglong2*>(
        g_part + ((size_t)blockIdx.x * SVOL + ((size_t)b0 * OO + o) * KK));
    ulonglong2* p1 = reinterpret_cast<ulonglong2*>(
        g_part + ((size_t)blockIdx.x * SVOL + ((size_t)b1 * OO + o) * KK));
    p0[0] = make_ulonglong2(sa[0], sa[1]);
    p0[1] = make_ulonglong2(sa[2], sa[3]);
    p0[2] = make_ulonglong2(sa[4], sa[5]);
    p0[3] = make_ulonglong2(sa[6], sa[7]);
    p1[0] = make_ulonglong2(sb[0], sb[1]);
    p1[1] = make_ulonglong2(sb[2], sb[3]);
    p1[2] = make_ulonglong2(sb[4], sb[5]);
    p1[3] = make_ulonglong2(sb[6], sb[7]);
}

// Reduce partials over NP slabs, squash over K=16 (R4 version, measured 7us).
// phase 0: vsum = v ; phase 1: vsum += v ; phase 2: out = v
__global__ void squash_kernel(float* __restrict__ out, int phase) {
    int idx = blockIdx.x * 256 + threadIdx.x;   // (b*O+o)*K + k
    float s = 0.0f;
#pragma unroll
    for (int p = 0; p < NP; p++) s += g_part[(size_t)p * SVOL + idx];

    float s2 = s * s;
    s2 += __shfl_xor_sync(0xffffffffu, s2, 1);
    s2 += __shfl_xor_sync(0xffffffffu, s2, 2);
    s2 += __shfl_xor_sync(0xffffffffu, s2, 4);
    s2 += __shfl_xor_sync(0xffffffffu, s2, 8);

    float scale = s2 / ((1.0f + s2) * sqrtf(s2 + 1e-7f));
    float v = scale * s;

    if (phase == 0)      g_vsum[idx] = v;
    else if (phase == 1) g_vsum[idx] += v;
    else                 out[idx] = v;
}

extern "C" void kernel_launch(void* const* d_in, const int* in_sizes, int n_in,
                              void* d_out, int out_size) {
    const float* a0 = (const float*)d_in[0];
    const float* a1 = (const float*)d_in[1];
    const float* x;
    const float* W;
    if (in_sizes[0] == BB * II * DD) { x = a0; W = a1; }
    else                             { x = a1; W = a0; }
    float* out = (float*)d_out;

    cudaFuncSetAttribute(pass_kernel<true>,
                         cudaFuncAttributeMaxDynamicSharedMemorySize, SMEM_BYTES);
    cudaFuncSetAttribute(pass_kernel<false>,
                         cudaFuncAttributeMaxDynamicSharedMemorySize, SMEM_BYTES);

    dim3 pg(II / IC, BB / BG);     // (64, 2) = 128 blocks, 512 threads
    const int rb = SVOL / 256;     // 128 blocks for squash

    pass_kernel<true><<<pg, 512, SMEM_BYTES>>>(x, W);    // s0 (uniform c)
    squash_kernel<<<rb, 256>>>(out, 0);                  // v0 -> Vsum

    pass_kernel<false><<<pg, 512, SMEM_BYTES>>>(x, W);   // s1 (vs v0)
    squash_kernel<<<rb, 256>>>(out, 1);                  // Vsum += v1

    pass_kernel<false><<<pg, 512, SMEM_BYTES>>>(x, W);   // s2 (vs v0+v1)
    squash_kernel<<<rb, 256>>>(out, 2);                  // v2 = output
}

// round 7
// speedup vs baseline: 1.0488x; 1.0362x over previous
#include <cuda_runtime.h>

// CapsuleLayer: x[B,I,D] fp32, W[I,O,D,K] fp32 -> v[B,O,K] fp32
// B=64, I=2048, D=8, O=32, K=16, 3 routing rounds.
// Routing logits linear in v => each round is one fused sweep over i.
// Round 7: 256-thr blocks x 2/SM (R5 pass, best measured) + SUB=2 slab
// barriers + R4 scalar squash (best measured) + 3 dummy launches so the
// ncu capture (-s 5 -c 1) lands on pass#2 instead of squash.

#define BB 64
#define II 2048
#define DD 8
#define OO 32
#define KK 16
#define BG 16            // b's per block (2 per thread)
#define IC 32            // i's per block
#define SUB 2            // i's per slab
#define NSLAB (IC/SUB)   // 16
#define NBUF 3
#define NP (II/IC)       // 64 partial slabs
#define SVOL (BB*OO*KK)  // 32768

#define WROWF 132                   // padded floats per o-row
#define WSLABF (SUB*OO*WROWF)       // 8448 floats
#define XROWF 12
#define XSLABF (SUB*BG*XROWF)       // 384 floats
#define SLABF  (WSLABF + XSLABF)    // 8832 floats
#define AG_OFF (NBUF*SLABF)         // 26496 floats
#define AGROW  33
#define SMEM_BYTES ((AG_OFF + BG*AGROW) * 4)   // 108096 B

__device__ float g_part[NP * SVOL];  // per-i-block partial s (8.4 MB)
__device__ float g_vsum[SVOL];       // running sum of squashed v's

// ---------- packed f32x2 helpers ----------
__device__ __forceinline__ unsigned long long pk2(float lo, float hi) {
    unsigned long long r;
    asm("mov.b64 %0, {%1, %2};" : "=l"(r) : "f"(lo), "f"(hi));
    return r;
}
__device__ __forceinline__ void upk2(unsigned long long v, float& lo, float& hi) {
    asm("mov.b64 {%0, %1}, %2;" : "=f"(lo), "=f"(hi) : "l"(v));
}
__device__ __forceinline__ unsigned long long fma2(unsigned long long a,
                                                   unsigned long long b,
                                                   unsigned long long c) {
    unsigned long long d;
    asm("fma.rn.f32x2 %0, %1, %2, %3;" : "=l"(d) : "l"(a), "l"(b), "l"(c));
    return d;
}

// ---------- cp.async helpers ----------
__device__ __forceinline__ void cp16(unsigned dst_smem, const void* src) {
    asm volatile("cp.async.cg.shared.global [%0], [%1], 16;"
                 :: "r"(dst_smem), "l"(src));
}
__device__ __forceinline__ void cp_commit() {
    asm volatile("cp.async.commit_group;");
}
template<int N>
__device__ __forceinline__ void cp_wait() {
    asm volatile("cp.async.wait_group %0;" :: "n"(N) : "memory");
}

// Stage one slab (SUB i's of W + x) into buffer `buf`. One commit group.
// 256 threads: W = 2048 float4 chunks (8/thread), x = 64 chunks (thr 0..63).
__device__ __forceinline__ void fill_slab(unsigned sm_addr,
                                          const float* __restrict__ W,
                                          const float* __restrict__ x,
                                          int i_base, int buf, int t, int bg) {
#pragma unroll
    for (int r = 0; r < 8; r++) {
        int c = t + r * 256;
        int isub = c >> 10, rem = c & 1023;
        int o = rem >> 5, w16 = rem & 31;
        const float* src = W + ((size_t)(i_base + isub) * OO + o) * (DD * KK) + w16 * 4;
        unsigned dst = sm_addr +
            (unsigned)((buf * SLABF + isub * (OO * WROWF) + o * WROWF + w16 * 4) * 4);
        cp16(dst, src);
    }
    if (t < SUB * BG * 2) {
        int isub = t >> 5, b = (t >> 1) & 15, half = t & 1;
        const float* src = x + ((size_t)(bg * BG + b) * II + (i_base + isub)) * DD + half * 4;
        unsigned dst = sm_addr +
            (unsigned)((buf * SLABF + WSLABF + isub * (BG * XROWF) + b * XROWF + half * 4) * 4);
        cp16(dst, src);
    }
    cp_commit();
}

// Fused routing pass. 256 threads: t = o*8 + tb; thread handles b = tb, tb+8.
// Warp = 4 o x 8 tb -> W smem reads have 8-way broadcast.
template<bool FIRST>
__global__ __launch_bounds__(256, 2)
void pass_kernel(const float* __restrict__ x, const float* __restrict__ W) {
    extern __shared__ float sm[];
    const unsigned sm_addr = (unsigned)__cvta_generic_to_shared(sm);
    float* ag = sm + AG_OFF;

    const int t  = threadIdx.x;
    const int o  = t >> 3;
    const int tb = t & 7;
    const int bg = blockIdx.y;
    const int b0 = bg * BG + tb;
    const int b1 = b0 + 8;
    const int i0 = blockIdx.x * IC;

    fill_slab(sm_addr, W, x, i0,       0, t, bg);
    fill_slab(sm_addr, W, x, i0 + SUB, 1, t, bg);

    unsigned long long Va[8], Vb[8];
    if (!FIRST) {
        const ulonglong2* vp0 =
            reinterpret_cast<const ulonglong2*>(g_vsum + ((size_t)b0 * OO + o) * KK);
        const ulonglong2* vp1 =
            reinterpret_cast<const ulonglong2*>(g_vsum + ((size_t)b1 * OO + o) * KK);
#pragma unroll
        for (int j = 0; j < 4; j++) {
            ulonglong2 q0 = vp0[j]; Va[2*j] = q0.x; Va[2*j+1] = q0.y;
            ulonglong2 q1 = vp1[j]; Vb[2*j] = q1.x; Vb[2*j+1] = q1.y;
        }
    }

    unsigned long long sa[8], sb[8];
#pragma unroll
    for (int j = 0; j < 8; j++) { sa[j] = 0ull; sb[j] = 0ull; }

    for (int s = 0; s < NSLAB; s++) {
        if (s + 1 < NSLAB) cp_wait<1>(); else cp_wait<0>();
        __syncthreads();   // slab s resident; all warps done with slab s-1
        if (s + 2 < NSLAB)
            fill_slab(sm_addr, W, x, i0 + (s + 2) * SUB, (s + 2) % NBUF, t, bg);

        const float* slab = sm + (s % NBUF) * SLABF;

#pragma unroll
        for (int isub = 0; isub < SUB; isub++) {
            float xf0[8], xf1[8];
            {
                const float4* xr0 = reinterpret_cast<const float4*>(
                    slab + WSLABF + isub * (BG * XROWF) + tb * XROWF);
                const float4* xr1 = reinterpret_cast<const float4*>(
                    slab + WSLABF + isub * (BG * XROWF) + (tb + 8) * XROWF);
                float4 a0 = xr0[0], a1 = xr0[1];
                float4 c0 = xr1[0], c1 = xr1[1];
                xf0[0]=a0.x; xf0[1]=a0.y; xf0[2]=a0.z; xf0[3]=a0.w;
                xf0[4]=a1.x; xf0[5]=a1.y; xf0[6]=a1.z; xf0[7]=a1.w;
                xf1[0]=c0.x; xf1[1]=c0.y; xf1[2]=c0.z; xf1[3]=c0.w;
                xf1[4]=c1.x; xf1[5]=c1.y; xf1[6]=c1.z; xf1[7]=c1.w;
            }

            unsigned long long ua[8], ub[8];
#pragma unroll
            for (int j = 0; j < 8; j++) { ua[j] = 0ull; ub[j] = 0ull; }

            const float* wrow = slab + isub * (OO * WROWF) + o * WROWF;
#pragma unroll
            for (int d = 0; d < DD; d++) {
                const ulonglong2* wp = reinterpret_cast<const ulonglong2*>(wrow + d * 16);
                unsigned long long xa2 = pk2(xf0[d], xf0[d]);
                unsigned long long xb2 = pk2(xf1[d], xf1[d]);
                ulonglong2 q0 = wp[0], q1 = wp[1];
                ua[0] = fma2(xa2, q0.x, ua[0]);  ub[0] = fma2(xb2, q0.x, ub[0]);
                ua[1] = fma2(xa2, q0.y, ua[1]);  ub[1] = fma2(xb2, q0.y, ub[1]);
                ua[2] = fma2(xa2, q1.x, ua[2]);  ub[2] = fma2(xb2, q1.x, ub[2]);
                ua[3] = fma2(xa2, q1.y, ua[3]);  ub[3] = fma2(xb2, q1.y, ub[3]);
                ulonglong2 q2 = wp[2], q3 = wp[3];
                ua[4] = fma2(xa2, q2.x, ua[4]);  ub[4] = fma2(xb2, q2.x, ub[4]);
                ua[5] = fma2(xa2, q2.y, ua[5]);  ub[5] = fma2(xb2, q2.y, ub[5]);
                ua[6] = fma2(xa2, q3.x, ua[6]);  ub[6] = fma2(xb2, q3.x, ub[6]);
                ua[7] = fma2(xa2, q3.y, ua[7]);  ub[7] = fma2(xb2, q3.y, ub[7]);
            }

            unsigned long long c2a, c2b;
            if (FIRST) {
                c2a = pk2(1.0f / OO, 1.0f / OO);
                c2b = c2a;
            } else {
                unsigned long long acca = 0ull, accb = 0ull;
#pragma unroll
                for (int j = 0; j < 8; j++) {
                    acca = fma2(ua[j], Va[j], acca);
                    accb = fma2(ub[j], Vb[j], accb);
                }
                float al, ah, bl2, bh;
                upk2(acca, al, ah);
                upk2(accb, bl2, bh);
                ag[tb * AGROW + o]       = al + ah;
                ag[(tb + 8) * AGROW + o] = bl2 + bh;
                __syncthreads();                 // barrier 1: agr visible

                // warp w: softmax rows w, w+8 (lane = o). No max-subtract:
                // |agr| <= |u||Vsum| = O(1), exp safe in fp32.
                {
                    int w = t >> 5, lane = t & 31;
                    float e0 = __expf(ag[w * AGROW + lane]);
                    float e1 = __expf(ag[(w + 8) * AGROW + lane]);
                    float s0 = e0, s1 = e1;
#pragma unroll
                    for (int st = 16; st > 0; st >>= 1) {
                        s0 += __shfl_xor_sync(0xffffffffu, s0, st);
                        s1 += __shfl_xor_sync(0xffffffffu, s1, st);
                    }
                    ag[w * AGROW + lane]       = __fdividef(e0, s0);
                    ag[(w + 8) * AGROW + lane] = __fdividef(e1, s1);
                }
                __syncthreads();                 // barrier 2: c visible

                float ca = ag[tb * AGROW + o];
                float cb = ag[(tb + 8) * AGROW + o];
                c2a = pk2(ca, ca);
                c2b = pk2(cb, cb);
            }

#pragma unroll
            for (int j = 0; j < 8; j++) {
                sa[j] = fma2(c2a, ua[j], sa[j]);
                sb[j] = fma2(c2b, ub[j], sb[j]);
            }
        }
    }

    ulonglong2* p0 = reinterpret_cast<ulonglong2*>(
        g_part + ((size_t)blockIdx.x * SVOL + ((size_t)b0 * OO + o) * KK));
    ulonglong2* p1 = reinterpret_cast<ulonglong2*>(
        g_part + ((size_t)blockIdx.x * SVOL + ((size_t)b1 * OO + o) * KK));
    p0[0] = make_ulonglong2(sa[0], sa[1]);
    p0[1] = make_ulonglong2(sa[2], sa[3]);
    p0[2] = make_ulonglong2(sa[4], sa[5]);
    p0[3] = make_ulonglong2(sa[6], sa[7]);
    p1[0] = make_ulonglong2(sb[0], sb[1]);
    p1[1] = make_ulonglong2(sb[2], sb[3]);
    p1[2] = make_ulonglong2(sb[4], sb[5]);
    p1[3] = make_ulonglong2(sb[6], sb[7]);
}

// Reduce partials over NP slabs, squash over K=16 (R4 version, measured 7us).
// phase 0: vsum = v ; phase 1: vsum += v ; phase 2: out = v
__global__ void squash_kernel(float* __restrict__ out, int phase) {
    int idx = blockIdx.x * 256 + threadIdx.x;   // (b*O+o)*K + k
    float s = 0.0f;
#pragma unroll
    for (int p = 0; p < NP; p++) s += g_part[(size_t)p * SVOL + idx];

    float s2 = s * s;
    s2 += __shfl_xor_sync(0xffffffffu, s2, 1);
    s2 += __shfl_xor_sync(0xffffffffu, s2, 2);
    s2 += __shfl_xor_sync(0xffffffffu, s2, 4);
    s2 += __shfl_xor_sync(0xffffffffu, s2, 8);

    float scale = s2 / ((1.0f + s2) * sqrtf(s2 + 1e-7f));
    float v = scale * s;

    if (phase == 0)      g_vsum[idx] = v;
    else if (phase == 1) g_vsum[idx] += v;
    else                 out[idx] = v;
}

// No-op: shifts ncu's -s 5 -c 1 capture window onto pass#2.
__global__ void dummy_kernel() {}

extern "C" void kernel_launch(void* const* d_in, const int* in_sizes, int n_in,
                              void* d_out, int out_size) {
    const float* a0 = (const float*)d_in[0];
    const float* a1 = (const float*)d_in[1];
    const float* x;
    const float* W;
    if (in_sizes[0] == BB * II * DD) { x = a0; W = a1; }
    else                             { x = a1; W = a0; }
    float* out = (float*)d_out;

    cudaFuncSetAttribute(pass_kernel<true>,
                         cudaFuncAttributeMaxDynamicSharedMemorySize, SMEM_BYTES);
    cudaFuncSetAttribute(pass_kernel<false>,
                         cudaFuncAttributeMaxDynamicSharedMemorySize, SMEM_BYTES);

    dim3 pg(II / IC, BB / BG);     // (64, 4) = 256 blocks, 256 threads
    const int rb = SVOL / 256;     // 128 blocks for squash

    dummy_kernel<<<1, 32>>>();     // launches 1..3: position pass#2 at #6
    dummy_kernel<<<1, 32>>>();
    dummy_kernel<<<1, 32>>>();

    pass_kernel<true><<<pg, 256, SMEM_BYTES>>>(x, W);    // #4: s0 (uniform c)
    squash_kernel<<<rb, 256>>>(out, 0);                  // #5: v0 -> Vsum

    pass_kernel<false><<<pg, 256, SMEM_BYTES>>>(x, W);   // #6: s1 (profiled)
    squash_kernel<<<rb, 256>>>(out, 1);                  // Vsum += v1

    pass_kernel<false><<<pg, 256, SMEM_BYTES>>>(x, W);   // s2 (vs v0+v1)
    squash_kernel<<<rb, 256>>>(out, 2);                  // v2 = output
}

// round 8
// speedup vs baseline: 1.1543x; 1.1005x over previous
#include <cuda_runtime.h>

// CapsuleLayer: x[B,I,D] fp32, W[I,O,D,K] fp32 -> v[B,O,K] fp32
// B=64, I=2048, D=8, O=32, K=16, 3 routing rounds.
// Routing logits linear in v => each round is one fused sweep over i.
// Round 8: grid = 74 x 4 = 296 blocks = 148 SMs x 2 exactly (no tail,
// occupancy at the register-capped max the whole pass). Variable i-range
// per block. SUB=1 slabs, 55KB smem. Squash with 4 accumulator chains.

#define BB 64
#define II 2048
#define DD 8
#define OO 32
#define KK 16
#define BG 16            // b's per block (2 per thread)
#define GX 74            // i-dimension blocks (74*4 = 296 = 148*2)
#define NBUF 3
#define SVOL (BB*OO*KK)  // 32768

#define WROWF 132                 // padded floats per o-row
#define WSLABF (OO*WROWF)         // 4224 floats (one i)
#define XROWF 12
#define XSLABF (BG*XROWF)         // 192 floats
#define SLABF  (WSLABF + XSLABF)  // 4416 floats
#define AG_OFF (NBUF*SLABF)       // 13248 floats
#define AGROW  33
#define SMEM_BYTES ((AG_OFF + BG*AGROW) * 4)   // 55104 B

__device__ float g_part[GX * SVOL];  // per-i-block partial s (9.7 MB)
__device__ float g_vsum[SVOL];       // running sum of squashed v's

// ---------- packed f32x2 helpers ----------
__device__ __forceinline__ unsigned long long pk2(float lo, float hi) {
    unsigned long long r;
    asm("mov.b64 %0, {%1, %2};" : "=l"(r) : "f"(lo), "f"(hi));
    return r;
}
__device__ __forceinline__ void upk2(unsigned long long v, float& lo, float& hi) {
    asm("mov.b64 {%0, %1}, %2;" : "=f"(lo), "=f"(hi) : "l"(v));
}
__device__ __forceinline__ unsigned long long fma2(unsigned long long a,
                                                   unsigned long long b,
                                                   unsigned long long c) {
    unsigned long long d;
    asm("fma.rn.f32x2 %0, %1, %2, %3;" : "=l"(d) : "l"(a), "l"(b), "l"(c));
    return d;
}

// ---------- cp.async helpers ----------
__device__ __forceinline__ void cp16(unsigned dst_smem, const void* src) {
    asm volatile("cp.async.cg.shared.global [%0], [%1], 16;"
                 :: "r"(dst_smem), "l"(src));
}
__device__ __forceinline__ void cp_commit() {
    asm volatile("cp.async.commit_group;");
}
template<int N>
__device__ __forceinline__ void cp_wait() {
    asm volatile("cp.async.wait_group %0;" :: "n"(N) : "memory");
}

// Stage one i (W tile + x column) into buffer `buf`. One commit group.
// 256 threads: W = 1024 float4 chunks (4/thread), x = 32 chunks (thr 0..31).
__device__ __forceinline__ void fill_slab(unsigned sm_addr,
                                          const float* __restrict__ W,
                                          const float* __restrict__ x,
                                          int i, int buf, int t, int bg) {
#pragma unroll
    for (int r = 0; r < 4; r++) {
        int c = t + r * 256;
        int o = c >> 5, w16 = c & 31;
        const float* src = W + ((size_t)i * OO + o) * (DD * KK) + w16 * 4;
        unsigned dst = sm_addr + (unsigned)((buf * SLABF + o * WROWF + w16 * 4) * 4);
        cp16(dst, src);
    }
    if (t < BG * 2) {
        int b = t >> 1, half = t & 1;
        const float* src = x + ((size_t)(bg * BG + b) * II + i) * DD + half * 4;
        unsigned dst = sm_addr +
            (unsigned)((buf * SLABF + WSLABF + b * XROWF + half * 4) * 4);
        cp16(dst, src);
    }
    cp_commit();
}

// Fused routing pass. 256 threads: t = o*8 + tb; thread handles b = tb, tb+8.
// Warp = 4 o x 8 tb -> W smem reads 8-way amortized.
template<bool FIRST>
__global__ __launch_bounds__(256, 2)
void pass_kernel(const float* __restrict__ x, const float* __restrict__ W) {
    extern __shared__ float sm[];
    const unsigned sm_addr = (unsigned)__cvta_generic_to_shared(sm);
    float* ag = sm + AG_OFF;

    const int t  = threadIdx.x;
    const int o  = t >> 3;
    const int tb = t & 7;
    const int bg = blockIdx.y;
    const int b0 = bg * BG + tb;
    const int b1 = b0 + 8;

    // variable i-range: block bx handles [ib, ie)  (27 or 28 i's)
    const int bx = blockIdx.x;
    const int ib = (bx * II) / GX;
    const int ie = ((bx + 1) * II) / GX;
    const int cnt = ie - ib;

    fill_slab(sm_addr, W, x, ib,     0, t, bg);
    fill_slab(sm_addr, W, x, ib + 1, 1, t, bg);

    unsigned long long Va[8], Vb[8];
    if (!FIRST) {
        const ulonglong2* vp0 =
            reinterpret_cast<const ulonglong2*>(g_vsum + ((size_t)b0 * OO + o) * KK);
        const ulonglong2* vp1 =
            reinterpret_cast<const ulonglong2*>(g_vsum + ((size_t)b1 * OO + o) * KK);
#pragma unroll
        for (int j = 0; j < 4; j++) {
            ulonglong2 q0 = vp0[j]; Va[2*j] = q0.x; Va[2*j+1] = q0.y;
            ulonglong2 q1 = vp1[j]; Vb[2*j] = q1.x; Vb[2*j+1] = q1.y;
        }
    }

    unsigned long long sa[8], sb[8];
#pragma unroll
    for (int j = 0; j < 8; j++) { sa[j] = 0ull; sb[j] = 0ull; }

    for (int s = 0; s < cnt; s++) {
        if (s + 1 < cnt) cp_wait<1>(); else cp_wait<0>();
        __syncthreads();   // slab s resident; all warps done with slab s-1
        if (s + 2 < cnt)
            fill_slab(sm_addr, W, x, ib + s + 2, (s + 2) % NBUF, t, bg);

        const float* slab = sm + (s % NBUF) * SLABF;

        float xf0[8], xf1[8];
        {
            const float4* xr0 = reinterpret_cast<const float4*>(
                slab + WSLABF + tb * XROWF);
            const float4* xr1 = reinterpret_cast<const float4*>(
                slab + WSLABF + (tb + 8) * XROWF);
            float4 a0 = xr0[0], a1 = xr0[1];
            float4 c0 = xr1[0], c1 = xr1[1];
            xf0[0]=a0.x; xf0[1]=a0.y; xf0[2]=a0.z; xf0[3]=a0.w;
            xf0[4]=a1.x; xf0[5]=a1.y; xf0[6]=a1.z; xf0[7]=a1.w;
            xf1[0]=c0.x; xf1[1]=c0.y; xf1[2]=c0.z; xf1[3]=c0.w;
            xf1[4]=c1.x; xf1[5]=c1.y; xf1[6]=c1.z; xf1[7]=c1.w;
        }

        unsigned long long ua[8], ub[8];
#pragma unroll
        for (int j = 0; j < 8; j++) { ua[j] = 0ull; ub[j] = 0ull; }

        const float* wrow = slab + o * WROWF;
#pragma unroll
        for (int d = 0; d < DD; d++) {
            const ulonglong2* wp = reinterpret_cast<const ulonglong2*>(wrow + d * 16);
            unsigned long long xa2 = pk2(xf0[d], xf0[d]);
            unsigned long long xb2 = pk2(xf1[d], xf1[d]);
            ulonglong2 q0 = wp[0], q1 = wp[1];
            ua[0] = fma2(xa2, q0.x, ua[0]);  ub[0] = fma2(xb2, q0.x, ub[0]);
            ua[1] = fma2(xa2, q0.y, ua[1]);  ub[1] = fma2(xb2, q0.y, ub[1]);
            ua[2] = fma2(xa2, q1.x, ua[2]);  ub[2] = fma2(xb2, q1.x, ub[2]);
            ua[3] = fma2(xa2, q1.y, ua[3]);  ub[3] = fma2(xb2, q1.y, ub[3]);
            ulonglong2 q2 = wp[2], q3 = wp[3];
            ua[4] = fma2(xa2, q2.x, ua[4]);  ub[4] = fma2(xb2, q2.x, ub[4]);
            ua[5] = fma2(xa2, q2.y, ua[5]);  ub[5] = fma2(xb2, q2.y, ub[5]);
            ua[6] = fma2(xa2, q3.x, ua[6]);  ub[6] = fma2(xb2, q3.x, ub[6]);
            ua[7] = fma2(xa2, q3.y, ua[7]);  ub[7] = fma2(xb2, q3.y, ub[7]);
        }

        unsigned long long c2a, c2b;
        if (FIRST) {
            c2a = pk2(1.0f / OO, 1.0f / OO);
            c2b = c2a;
        } else {
            unsigned long long acca = 0ull, accb = 0ull;
#pragma unroll
            for (int j = 0; j < 8; j++) {
                acca = fma2(ua[j], Va[j], acca);
                accb = fma2(ub[j], Vb[j], accb);
            }
            float al, ah, bl2, bh;
            upk2(acca, al, ah);
            upk2(accb, bl2, bh);
            ag[tb * AGROW + o]       = al + ah;
            ag[(tb + 8) * AGROW + o] = bl2 + bh;
            __syncthreads();                 // barrier 1: agr visible

            // warp w: softmax rows w, w+8 (lane = o). No max-subtract:
            // |agr| <= |u||Vsum| = O(1), exp safe in fp32.
            {
                int w = t >> 5, lane = t & 31;
                float e0 = __expf(ag[w * AGROW + lane]);
                float e1 = __expf(ag[(w + 8) * AGROW + lane]);
                float s0 = e0, s1 = e1;
#pragma unroll
                for (int st = 16; st > 0; st >>= 1) {
                    s0 += __shfl_xor_sync(0xffffffffu, s0, st);
                    s1 += __shfl_xor_sync(0xffffffffu, s1, st);
                }
                ag[w * AGROW + lane]       = __fdividef(e0, s0);
                ag[(w + 8) * AGROW + lane] = __fdividef(e1, s1);
            }
            __syncthreads();                 // barrier 2: c visible

            float ca = ag[tb * AGROW + o];
            float cb = ag[(tb + 8) * AGROW + o];
            c2a = pk2(ca, ca);
            c2b = pk2(cb, cb);
        }

#pragma unroll
        for (int j = 0; j < 8; j++) {
            sa[j] = fma2(c2a, ua[j], sa[j]);
            sb[j] = fma2(c2b, ub[j], sb[j]);
        }
    }

    ulonglong2* p0 = reinterpret_cast<ulonglong2*>(
        g_part + ((size_t)bx * SVOL + ((size_t)b0 * OO + o) * KK));
    ulonglong2* p1 = reinterpret_cast<ulonglong2*>(
        g_part + ((size_t)bx * SVOL + ((size_t)b1 * OO + o) * KK));
    p0[0] = make_ulonglong2(sa[0], sa[1]);
    p0[1] = make_ulonglong2(sa[2], sa[3]);
    p0[2] = make_ulonglong2(sa[4], sa[5]);
    p0[3] = make_ulonglong2(sa[6], sa[7]);
    p1[0] = make_ulonglong2(sb[0], sb[1]);
    p1[1] = make_ulonglong2(sb[2], sb[3]);
    p1[2] = make_ulonglong2(sb[4], sb[7-5]);  // sb[2]
    p1[2] = make_ulonglong2(sb[4], sb[5]);
    p1[3] = make_ulonglong2(sb[6], sb[7]);
}

// Reduce partials over GX slabs (4 independent chains for MLP), squash K=16.
// phase 0: vsum = v ; phase 1: vsum += v ; phase 2: out = v
__global__ void squash_kernel(float* __restrict__ out, int phase) {
    int idx = blockIdx.x * 256 + threadIdx.x;   // (b*O+o)*K + k
    float a0 = 0.f, a1 = 0.f, a2 = 0.f, a3 = 0.f;
#pragma unroll
    for (int p = 0; p + 4 <= GX; p += 4) {
        a0 += g_part[(size_t)(p + 0) * SVOL + idx];
        a1 += g_part[(size_t)(p + 1) * SVOL + idx];
        a2 += g_part[(size_t)(p + 2) * SVOL + idx];
        a3 += g_part[(size_t)(p + 3) * SVOL + idx];
    }
    a0 += g_part[(size_t)(GX - 2) * SVOL + idx];
    a1 += g_part[(size_t)(GX - 1) * SVOL + idx];
    float s = (a0 + a1) + (a2 + a3);

    float s2 = s * s;
    s2 += __shfl_xor_sync(0xffffffffu, s2, 1);
    s2 += __shfl_xor_sync(0xffffffffu, s2, 2);
    s2 += __shfl_xor_sync(0xffffffffu, s2, 4);
    s2 += __shfl_xor_sync(0xffffffffu, s2, 8);

    float scale = s2 / ((1.0f + s2) * sqrtf(s2 + 1e-7f));
    float v = scale * s;

    if (phase == 0)      g_vsum[idx] = v;
    else if (phase == 1) g_vsum[idx] += v;
    else                 out[idx] = v;
}

// No-op: shifts ncu's -s 5 -c 1 capture window onto pass#3.
__global__ void dummy_kernel() {}

extern "C" void kernel_launch(void* const* d_in, const int* in_sizes, int n_in,
                              void* d_out, int out_size) {
    const float* a0 = (const float*)d_in[0];
    const float* a1 = (const float*)d_in[1];
    const float* x;
    const float* W;
    if (in_sizes[0] == BB * II * DD) { x = a0; W = a1; }
    else                             { x = a1; W = a0; }
    float* out = (float*)d_out;

    cudaFuncSetAttribute(pass_kernel<true>,
                         cudaFuncAttributeMaxDynamicSharedMemorySize, SMEM_BYTES);
    cudaFuncSetAttribute(pass_kernel<false>,
                         cudaFuncAttributeMaxDynamicSharedMemorySize, SMEM_BYTES);

    dim3 pg(GX, BB / BG);          // (74, 4) = 296 blocks = 148 SMs x 2
    const int rb = SVOL / 256;     // 128 blocks for squash

    dummy_kernel<<<1, 32>>>();                           // #1 (aligns capture)

    pass_kernel<true><<<pg, 256, SMEM_BYTES>>>(x, W);    // #2: s0 (uniform c)
    squash_kernel<<<rb, 256>>>(out, 0);                  // #3: v0 -> Vsum

    pass_kernel<false><<<pg, 256, SMEM_BYTES>>>(x, W);   // #4: s1 (vs v0)
    squash_kernel<<<rb, 256>>>(out, 1);                  // #5: Vsum += v1

    pass_kernel<false><<<pg, 256, SMEM_BYTES>>>(x, W);   // #6: s2 (profiled)
    squash_kernel<<<rb, 256>>>(out, 2);                  // #7: v2 = output
}